// round 2
// baseline (speedup 1.0000x reference)
#include <cuda_runtime.h>
#include <math.h>

#define HIDDEN   2048
#define NEXP     64
#define TOPK     6
#define NGRP     8
#define EPG      8      // experts per group
#define TOPKG    4
#define INTER    1024
#define SHINTER  4096
#define RSCALE   2.5f
#define MAXT     1024
#define ICHUNK   128
#define TTILE    32

// ---------------- scratch (device globals; no allocation allowed) ----------
__device__ int   g_cnt[NEXP];
__device__ int   g_tok[NEXP * MAXT];
__device__ float g_wt [NEXP * MAXT];
__device__ float g_h1 [MAXT * SHINTER];   // shared-expert intermediate, 16MB

// ---------------- zero expert counters -------------------------------------
__global__ void k_zero() {
    if (threadIdx.x < NEXP) g_cnt[threadIdx.x] = 0;
}

// ---------------- gating: sigmoid + group-limited top-k --------------------
// one block per token, 64 threads (one per expert)
__global__ void k_gate(const float* __restrict__ x,
                       const float* __restrict__ gw,
                       const float* __restrict__ gb) {
    __shared__ float xs[HIDDEN];
    __shared__ float sc[NEXP];   // sigmoid scores (unbiased)
    __shared__ float sb[NEXP];   // bias-corrected scores
    const int t = blockIdx.x;
    const float* xr = x + (size_t)t * HIDDEN;
    for (int i = threadIdx.x; i < HIDDEN / 4; i += blockDim.x)
        ((float4*)xs)[i] = ((const float4*)xr)[i];
    __syncthreads();

    {
        const int e = threadIdx.x;
        const float4* w4 = (const float4*)(gw + (size_t)e * HIDDEN);
        float acc = 0.f;
#pragma unroll 8
        for (int i = 0; i < HIDDEN / 4; i++) {
            float4 wv = w4[i];
            float4 xv = ((float4*)xs)[i];
            acc += wv.x * xv.x + wv.y * xv.y + wv.z * xv.z + wv.w * xv.w;
        }
        float s = 1.f / (1.f + expf(-acc));
        sc[e] = s;
        sb[e] = s + gb[e];
    }
    __syncthreads();

    if (threadIdx.x == 0) {
        // group score = sum of top-2 biased scores in group
        float gs[NGRP];
        for (int g = 0; g < NGRP; g++) {
            float m1 = -1e30f, m2 = -1e30f;
            for (int j = 0; j < EPG; j++) {
                float v = sb[g * EPG + j];
                if (v > m1) { m2 = m1; m1 = v; }
                else if (v > m2) { m2 = v; }
            }
            gs[g] = m1 + m2;
        }
        // top-4 groups
        bool gsel[NGRP];
        for (int g = 0; g < NGRP; g++) gsel[g] = false;
        for (int r = 0; r < TOPKG; r++) {
            int bi = -1; float bv = -1e30f;
            for (int g = 0; g < NGRP; g++)
                if (!gsel[g] && gs[g] > bv) { bv = gs[g]; bi = g; }
            gsel[bi] = true;
        }
        // top-6 experts among selected groups (by biased score)
        bool esel[NEXP];
        for (int e = 0; e < NEXP; e++) esel[e] = false;
        int   eidx[TOPK];
        float wv[TOPK];
        float wsum = 0.f;
        for (int r = 0; r < TOPK; r++) {
            int bi = -1; float bv = -INFINITY;
            for (int e = 0; e < NEXP; e++) {
                if (!gsel[e / EPG] || esel[e]) continue;
                if (sb[e] > bv) { bv = sb[e]; bi = e; }
            }
            esel[bi] = true;
            eidx[r] = bi;
            wv[r] = sc[bi];          // combine weight from UNBIASED score
            wsum += sc[bi];
        }
        float inv = RSCALE / (wsum + 1e-20f);
        for (int r = 0; r < TOPK; r++) {
            int e = eidx[r];
            int p = atomicAdd(&g_cnt[e], 1);
            g_tok[e * MAXT + p] = t;
            g_wt [e * MAXT + p] = wv[r] * inv;
        }
    }
}

// ---------------- generic tiled fp32 GEMM: C = op(A[MxK] @ B[KxN]) ---------
// BM=BN=64, BK=32, 256 threads, 4x4 accum per thread
template <bool RELU2>
__global__ __launch_bounds__(256) void k_gemm(const float* __restrict__ A,
                                              const float* __restrict__ B,
                                              float* __restrict__ C,
                                              int M, int N, int K) {
    __shared__ float As[32][65];   // stored [k][m], padded
    __shared__ float Bs[32][64];   // stored [k][n]
    const int tid = threadIdx.x;
    const int tx = tid & 15;       // n dir
    const int ty = tid >> 4;       // m dir
    const int m0 = blockIdx.y * 64;
    const int n0 = blockIdx.x * 64;

    float acc[4][4];
#pragma unroll
    for (int i = 0; i < 4; i++)
#pragma unroll
        for (int j = 0; j < 4; j++) acc[i][j] = 0.f;

    const int arow = tid >> 2;       // 0..63
    const int akq  = tid & 3;        // float4 group (two per 32-k)
    const int brow = tid >> 4;       // 0..15 (two rows per 32-k)
    const int bcol = (tid & 15) * 4;

    for (int k0 = 0; k0 < K; k0 += 32) {
#pragma unroll
        for (int h = 0; h < 2; h++) {
            float4 av = *(const float4*)(A + (size_t)(m0 + arow) * K + k0 + (akq + 4 * h) * 4);
            As[(akq + 4 * h) * 4 + 0][arow] = av.x;
            As[(akq + 4 * h) * 4 + 1][arow] = av.y;
            As[(akq + 4 * h) * 4 + 2][arow] = av.z;
            As[(akq + 4 * h) * 4 + 3][arow] = av.w;
            float4 bv = *(const float4*)(B + (size_t)(k0 + brow + 16 * h) * N + n0 + bcol);
            *(float4*)&Bs[brow + 16 * h][bcol] = bv;
        }
        __syncthreads();
#pragma unroll
        for (int kk = 0; kk < 32; kk++) {
            float a0 = As[kk][ty * 4 + 0];
            float a1 = As[kk][ty * 4 + 1];
            float a2 = As[kk][ty * 4 + 2];
            float a3 = As[kk][ty * 4 + 3];
            float4 b4 = *(float4*)&Bs[kk][tx * 4];
            acc[0][0] += a0 * b4.x; acc[0][1] += a0 * b4.y; acc[0][2] += a0 * b4.z; acc[0][3] += a0 * b4.w;
            acc[1][0] += a1 * b4.x; acc[1][1] += a1 * b4.y; acc[1][2] += a1 * b4.z; acc[1][3] += a1 * b4.w;
            acc[2][0] += a2 * b4.x; acc[2][1] += a2 * b4.y; acc[2][2] += a2 * b4.z; acc[2][3] += a2 * b4.w;
            acc[3][0] += a3 * b4.x; acc[3][1] += a3 * b4.y; acc[3][2] += a3 * b4.z; acc[3][3] += a3 * b4.w;
        }
        __syncthreads();
    }
#pragma unroll
    for (int i = 0; i < 4; i++) {
        float* crow = C + (size_t)(m0 + ty * 4 + i) * N + n0 + tx * 4;
#pragma unroll
        for (int j = 0; j < 4; j++) {
            float v = acc[i][j];
            if (RELU2) { v = fmaxf(v, 0.f); v = v * v; }
            crow[j] = v;
        }
    }
}

// ---------------- routed experts: fused gather->GEMM1->relu2*w->GEMM2 -----
// block = (expert, inter-chunk of 128). Loops over that expert's token list
// in tiles of 32. Scatters via atomicAdd into out.
__global__ __launch_bounds__(256) void k_routed(const float* __restrict__ x,
                                                const float* __restrict__ w1,
                                                const float* __restrict__ w2,
                                                float* __restrict__ out) {
    const int e  = blockIdx.x / (INTER / ICHUNK);
    const int ic = blockIdx.x % (INTER / ICHUNK);
    const int cnt = g_cnt[e];
    if (cnt == 0) return;

    __shared__ float Xs[TTILE][33];
    __shared__ float Ws[32][ICHUNK];
    __shared__ float Hs[TTILE][ICHUNK];
    __shared__ int   stok[TTILE];
    __shared__ float swt [TTILE];

    const float* w1e = w1 + (size_t)e * HIDDEN * INTER + ic * ICHUNK;
    const float* w2e = w2 + ((size_t)e * INTER + (size_t)ic * ICHUNK) * HIDDEN;
    const int tid = threadIdx.x;
    const int tg = tid >> 4;            // 0..15 -> token pair
    const int ig = (tid & 15) * 8;      // 8 inter-cols

    for (int t0 = 0; t0 < cnt; t0 += TTILE) {
        const int nt = min(TTILE, cnt - t0);
        __syncthreads();
        if (tid < TTILE) {
            int valid = (tid < nt);
            stok[tid] = valid ? g_tok[e * MAXT + t0 + tid] : g_tok[e * MAXT + t0];
            swt [tid] = valid ? g_wt [e * MAXT + t0 + tid] : 0.f;
        }
        __syncthreads();

        // ---- GEMM1: Hs = relu2(Xg @ W1chunk) * route_w ----
        float acc[2][8];
#pragma unroll
        for (int i = 0; i < 2; i++)
#pragma unroll
            for (int j = 0; j < 8; j++) acc[i][j] = 0.f;

        for (int k0 = 0; k0 < HIDDEN; k0 += 32) {
            {   // load X tile (gathered rows): 32 tok x 32 k
                int tt = tid >> 3;
                int kq = tid & 7;
                float4 v = *(const float4*)(x + (size_t)stok[tt] * HIDDEN + k0 + kq * 4);
                Xs[tt][kq * 4 + 0] = v.x;
                Xs[tt][kq * 4 + 1] = v.y;
                Xs[tt][kq * 4 + 2] = v.z;
                Xs[tt][kq * 4 + 3] = v.w;
            }
#pragma unroll
            for (int r = 0; r < 4; r++) {   // load W1 tile: 32 k x 128 i
                int kr = r * 8 + (tid >> 5);
                int cq = (tid & 31);
                float4 v = *(const float4*)(w1e + (size_t)(k0 + kr) * INTER + cq * 4);
                *(float4*)&Ws[kr][cq * 4] = v;
            }
            __syncthreads();
#pragma unroll
            for (int kk = 0; kk < 32; kk++) {
                float a0 = Xs[2 * tg + 0][kk];
                float a1 = Xs[2 * tg + 1][kk];
                float4 b0 = *(float4*)&Ws[kk][ig];
                float4 b1 = *(float4*)&Ws[kk][ig + 4];
                acc[0][0] += a0 * b0.x; acc[0][1] += a0 * b0.y; acc[0][2] += a0 * b0.z; acc[0][3] += a0 * b0.w;
                acc[0][4] += a0 * b1.x; acc[0][5] += a0 * b1.y; acc[0][6] += a0 * b1.z; acc[0][7] += a0 * b1.w;
                acc[1][0] += a1 * b0.x; acc[1][1] += a1 * b0.y; acc[1][2] += a1 * b0.z; acc[1][3] += a1 * b0.w;
                acc[1][4] += a1 * b1.x; acc[1][5] += a1 * b1.y; acc[1][6] += a1 * b1.z; acc[1][7] += a1 * b1.w;
            }
            __syncthreads();
        }
        {
            float w0 = swt[2 * tg + 0], w1v = swt[2 * tg + 1];
#pragma unroll
            for (int j = 0; j < 8; j++) {
                float v0 = fmaxf(acc[0][j], 0.f);
                float v1 = fmaxf(acc[1][j], 0.f);
                Hs[2 * tg + 0][ig + j] = v0 * v0 * w0;
                Hs[2 * tg + 1][ig + j] = v1 * v1 * w1v;
            }
        }
        __syncthreads();

        // ---- GEMM2: out[tok, :] += Hs @ W2chunk  (atomic scatter) ----
        for (int c0 = 0; c0 < HIDDEN; c0 += 256) {
            const int col = c0 + tid;
            float acc2[TTILE];
#pragma unroll
            for (int t = 0; t < TTILE; t++) acc2[t] = 0.f;
            for (int i = 0; i < ICHUNK; i += 4) {
                float wa = w2e[(size_t)(i + 0) * HIDDEN + col];
                float wb = w2e[(size_t)(i + 1) * HIDDEN + col];
                float wc = w2e[(size_t)(i + 2) * HIDDEN + col];
                float wd = w2e[(size_t)(i + 3) * HIDDEN + col];
#pragma unroll
                for (int t = 0; t < TTILE; t++) {
                    float4 hv = *(float4*)&Hs[t][i];
                    acc2[t] += hv.x * wa + hv.y * wb + hv.z * wc + hv.w * wd;
                }
            }
            for (int t = 0; t < nt; t++)
                atomicAdd(&out[(size_t)stok[t] * HIDDEN + col], acc2[t]);
        }
    }
}

// ---------------------------------------------------------------------------
extern "C" void kernel_launch(void* const* d_in, const int* in_sizes, int n_in,
                              void* d_out, int out_size) {
    const float* x   = (const float*)d_in[0];   // [2,512,2048]
    const float* gw  = (const float*)d_in[1];   // [64,2048]
    const float* gb  = (const float*)d_in[2];   // [64]
    const float* wup = (const float*)d_in[3];   // [2048,4096]
    const float* wdn = (const float*)d_in[4];   // [4096,2048]
    const float* w1  = (const float*)d_in[5];   // [64,2048,1024]
    const float* w2  = (const float*)d_in[6];   // [64,1024,2048]
    float* out = (float*)d_out;                 // [2,512,2048] fp32

    const int T = in_sizes[0] / HIDDEN;         // 1024

    float* h1 = nullptr;
    cudaGetSymbolAddress((void**)&h1, g_h1);

    k_zero<<<1, 64>>>();
    k_gate<<<T, 64>>>(x, gw, gb);
    // shared expert MLP
    k_gemm<true ><<<dim3(SHINTER / 64, T / 64), 256>>>(x,  wup, h1,  T, SHINTER, HIDDEN);
    k_gemm<false><<<dim3(HIDDEN  / 64, T / 64), 256>>>(h1, wdn, out, T, HIDDEN,  SHINTER);
    // routed experts (accumulates on top of shared output)
    k_routed<<<NEXP * (INTER / ICHUNK), 256>>>(x, w1, w2, out);
}

// round 3
// speedup vs baseline: 4.4202x; 4.4202x over previous
#include <cuda_runtime.h>
#include <math.h>
#include <stdint.h>

#define HIDDEN   2048
#define NEXP     64
#define TOPK     6
#define NGRP     8
#define EPG      8
#define TOPKG    4
#define INTER    1024
#define SHINTER  4096
#define RSCALE   2.5f
#define MAXT     1024
#define ACT_ROWS 14336   // max padded routed rows: 6144 + 64*127, rounded up

#define ASTR 36          // A smem row stride (floats)
#define BSTR 72          // B smem row stride (floats)

// ---------------- scratch ---------------------------------------------------
__device__ int   g_cnt[NEXP];
__device__ int   g_off[NEXP];                 // padded exclusive offsets into g_act
__device__ int   g_tok[NEXP * MAXT];
__device__ float g_wt [NEXP * MAXT];
__device__ float g_h1 [MAXT * SHINTER];       // shared-expert intermediate (16MB)
__device__ float g_act[(size_t)ACT_ROWS * INTER]; // routed intermediate (56MB)

// ---------------- tiny kernels ----------------------------------------------
__global__ void k_zero() {
    if (threadIdx.x < NEXP) g_cnt[threadIdx.x] = 0;
}
__global__ void k_scan() {
    if (threadIdx.x == 0) {
        int acc = 0;
        for (int e = 0; e < NEXP; e++) {
            g_off[e] = acc;
            acc += (g_cnt[e] + 127) & ~127;
        }
    }
}

// ---------------- gating ----------------------------------------------------
__global__ void k_gate(const float* __restrict__ x,
                       const float* __restrict__ gw,
                       const float* __restrict__ gb) {
    __shared__ float xs[HIDDEN];
    __shared__ float sc[NEXP];
    __shared__ float sb[NEXP];
    const int t = blockIdx.x;
    const float* xr = x + (size_t)t * HIDDEN;
    for (int i = threadIdx.x; i < HIDDEN / 4; i += blockDim.x)
        ((float4*)xs)[i] = ((const float4*)xr)[i];
    __syncthreads();

    {
        const int e = threadIdx.x;
        const float4* w4 = (const float4*)(gw + (size_t)e * HIDDEN);
        float acc = 0.f;
#pragma unroll 8
        for (int i = 0; i < HIDDEN / 4; i++) {
            float4 wv = w4[i];
            float4 xv = ((float4*)xs)[i];
            acc += wv.x * xv.x + wv.y * xv.y + wv.z * xv.z + wv.w * xv.w;
        }
        float s = 1.f / (1.f + expf(-acc));
        sc[e] = s;
        sb[e] = s + gb[e];
    }
    __syncthreads();

    if (threadIdx.x == 0) {
        float gs[NGRP];
        for (int g = 0; g < NGRP; g++) {
            float m1 = -1e30f, m2 = -1e30f;
            for (int j = 0; j < EPG; j++) {
                float v = sb[g * EPG + j];
                if (v > m1) { m2 = m1; m1 = v; }
                else if (v > m2) { m2 = v; }
            }
            gs[g] = m1 + m2;
        }
        bool gsel[NGRP];
        for (int g = 0; g < NGRP; g++) gsel[g] = false;
        for (int r = 0; r < TOPKG; r++) {
            int bi = -1; float bv = -1e30f;
            for (int g = 0; g < NGRP; g++)
                if (!gsel[g] && gs[g] > bv) { bv = gs[g]; bi = g; }
            gsel[bi] = true;
        }
        bool esel[NEXP];
        for (int e = 0; e < NEXP; e++) esel[e] = false;
        int   eidx[TOPK];
        float wv[TOPK];
        float wsum = 0.f;
        for (int r = 0; r < TOPK; r++) {
            int bi = -1; float bv = -INFINITY;
            for (int e = 0; e < NEXP; e++) {
                if (!gsel[e / EPG] || esel[e]) continue;
                if (sb[e] > bv) { bv = sb[e]; bi = e; }
            }
            esel[bi] = true;
            eidx[r] = bi;
            wv[r] = sc[bi];
            wsum += sc[bi];
        }
        float inv = RSCALE / (wsum + 1e-20f);
        for (int r = 0; r < TOPK; r++) {
            int e = eidx[r];
            int p = atomicAdd(&g_cnt[e], 1);
            g_tok[e * MAXT + p] = t;
            g_wt [e * MAXT + p] = wv[r] * inv;
        }
    }
}

// ---------------- tf32 helpers ----------------------------------------------
__device__ __forceinline__ uint32_t f2tf(float x) {
    uint32_t u;
    asm("cvt.rna.tf32.f32 %0, %1;" : "=r"(u) : "f"(x));
    return u;
}
__device__ __forceinline__ void mma8(float4& d, const uint32_t a[4],
                                     uint32_t b0, uint32_t b1) {
    asm("mma.sync.aligned.m16n8k8.row.col.f32.tf32.tf32.f32 "
        "{%0,%1,%2,%3},{%4,%5,%6,%7},{%8,%9},{%0,%1,%2,%3};"
        : "+f"(d.x), "+f"(d.y), "+f"(d.z), "+f"(d.w)
        : "r"(a[0]), "r"(a[1]), "r"(a[2]), "r"(a[3]), "r"(b0), "r"(b1));
}

// ---------------- tf32 GEMM: BM=128 BN=64 BK=32, 256 thr, warp tile 32x32 ---
// MODE 0: shared-up   C = relu2(A@B),           A direct, store
// MODE 1: shared-down C = A@B,                  A direct, store
// MODE 2: routed-up   g_act = relu2(Xg@W1[e])*w, A gathered by token list
// MODE 3: routed-down out += g_act[e]@W2[e],     atomic scatter by token list
template <int MODE>
__global__ __launch_bounds__(256) void k_mm(const float* __restrict__ A,
                                            const float* __restrict__ Bg,
                                            float* __restrict__ C,
                                            int K, int N) {
    __shared__ float As[128 * ASTR];
    __shared__ float Bs[32 * BSTR];
    __shared__ int   stok[128];
    __shared__ float swt [128];

    const int tid  = threadIdx.x;
    const int lane = tid & 31;
    const int warp = tid >> 5;
    const int wm   = warp & 3;      // 4 warps along M
    const int wn   = warp >> 2;     // 2 warps along N
    const int grp  = lane >> 2;
    const int tg   = lane & 3;
    const int n0   = blockIdx.x * 64;

    int e = 0, cnt = 0, m_begin, m_end;
    const float* B = Bg;
    const float* Abase = A;
    if (MODE <= 1) {
        m_begin = blockIdx.y * 128;
        m_end   = m_begin + 128;
    } else {
        e   = blockIdx.y;
        cnt = g_cnt[e];
        if (cnt == 0) return;
        m_begin = 0;
        m_end   = (cnt + 127) & ~127;
        B = Bg + (size_t)e * K * N;                    // w1[e] or w2[e]
        if (MODE == 3) Abase = A + (size_t)g_off[e] * K;
    }

    for (int m0 = m_begin; m0 < m_end; m0 += 128) {
        if (MODE >= 2) {
            __syncthreads();
            if (tid < 128) {
                int r = m0 + tid;
                int valid = r < cnt;
                stok[tid] = g_tok[e * MAXT + (valid ? r : 0)];
                swt [tid] = valid ? g_wt[e * MAXT + r] : 0.f;
            }
            __syncthreads();
        }

        // fixed row pointers for this tile (4 rows per thread)
        const float* aptr[4];
#pragma unroll
        for (int i = 0; i < 4; i++) {
            int r = (tid >> 3) + 32 * i;
            if (MODE == 2)      aptr[i] = A + (size_t)stok[r] * K;
            else if (MODE == 3) aptr[i] = Abase + (size_t)(m0 + r) * K;
            else                aptr[i] = A + (size_t)(m0 + r) * K;
        }

        float4 acc[2][4];
#pragma unroll
        for (int i = 0; i < 2; i++)
#pragma unroll
            for (int j = 0; j < 4; j++) acc[i][j] = make_float4(0.f, 0.f, 0.f, 0.f);

        for (int k0 = 0; k0 < K; k0 += 32) {
#pragma unroll
            for (int i = 0; i < 4; i++) {
                float4 v = *(const float4*)(aptr[i] + k0 + (tid & 7) * 4);
                *(float4*)&As[((tid >> 3) + 32 * i) * ASTR + (tid & 7) * 4] = v;
            }
#pragma unroll
            for (int i = 0; i < 2; i++) {
                int r = (tid >> 4) + 16 * i;
                float4 v = *(const float4*)(B + (size_t)(k0 + r) * N + n0 + (tid & 15) * 4);
                *(float4*)&Bs[r * BSTR + (tid & 15) * 4] = v;
            }
            __syncthreads();
#pragma unroll
            for (int kk = 0; kk < 32; kk += 8) {
                uint32_t af[2][4];
#pragma unroll
                for (int mt = 0; mt < 2; mt++) {
                    int rb = (wm * 32 + mt * 16 + grp) * ASTR + kk;
                    af[mt][0] = f2tf(As[rb + tg]);
                    af[mt][1] = f2tf(As[rb + 8 * ASTR + tg]);
                    af[mt][2] = f2tf(As[rb + tg + 4]);
                    af[mt][3] = f2tf(As[rb + 8 * ASTR + tg + 4]);
                }
#pragma unroll
                for (int nt = 0; nt < 4; nt++) {
                    int cb = (kk + tg) * BSTR + wn * 32 + nt * 8 + grp;
                    uint32_t b0 = f2tf(Bs[cb]);
                    uint32_t b1 = f2tf(Bs[cb + 4 * BSTR]);
                    mma8(acc[0][nt], af[0], b0, b1);
                    mma8(acc[1][nt], af[1], b0, b1);
                }
            }
            __syncthreads();
        }

        // epilogue
#pragma unroll
        for (int mt = 0; mt < 2; mt++) {
            int r0 = wm * 32 + mt * 16 + grp;
            int r1 = r0 + 8;
#pragma unroll
            for (int nt = 0; nt < 4; nt++) {
                int c = n0 + wn * 32 + nt * 8 + tg * 2;
                float4 v = acc[mt][nt];
                if (MODE == 0 || MODE == 2) {
                    v.x = fmaxf(v.x, 0.f); v.x *= v.x;
                    v.y = fmaxf(v.y, 0.f); v.y *= v.y;
                    v.z = fmaxf(v.z, 0.f); v.z *= v.z;
                    v.w = fmaxf(v.w, 0.f); v.w *= v.w;
                }
                if (MODE == 2) {
                    float w0 = swt[r0], w1 = swt[r1];
                    v.x *= w0; v.y *= w0; v.z *= w1; v.w *= w1;
                }
                if (MODE == 3) {
                    if (m0 + r0 < cnt) {
                        float* o = C + (size_t)stok[r0] * N + c;
                        atomicAdd(o, v.x);
                        atomicAdd(o + 1, v.y);
                    }
                    if (m0 + r1 < cnt) {
                        float* o = C + (size_t)stok[r1] * N + c;
                        atomicAdd(o, v.z);
                        atomicAdd(o + 1, v.w);
                    }
                } else if (MODE == 2) {
                    float* crow = g_act + (size_t)(g_off[e] + m0 + r0) * N + c;
                    *(float2*)crow = make_float2(v.x, v.y);
                    crow = g_act + (size_t)(g_off[e] + m0 + r1) * N + c;
                    *(float2*)crow = make_float2(v.z, v.w);
                } else {
                    *(float2*)(C + (size_t)(m0 + r0) * N + c) = make_float2(v.x, v.y);
                    *(float2*)(C + (size_t)(m0 + r1) * N + c) = make_float2(v.z, v.w);
                }
            }
        }
    }
}

// ---------------------------------------------------------------------------
extern "C" void kernel_launch(void* const* d_in, const int* in_sizes, int n_in,
                              void* d_out, int out_size) {
    const float* x   = (const float*)d_in[0];   // [2,512,2048]
    const float* gw  = (const float*)d_in[1];   // [64,2048]
    const float* gb  = (const float*)d_in[2];   // [64]
    const float* wup = (const float*)d_in[3];   // [2048,4096]
    const float* wdn = (const float*)d_in[4];   // [4096,2048]
    const float* w1  = (const float*)d_in[5];   // [64,2048,1024]
    const float* w2  = (const float*)d_in[6];   // [64,1024,2048]
    float* out = (float*)d_out;                 // [2,512,2048] fp32

    const int T = in_sizes[0] / HIDDEN;         // 1024

    float* h1 = nullptr;
    cudaGetSymbolAddress((void**)&h1, g_h1);
    float* act = nullptr;
    cudaGetSymbolAddress((void**)&act, g_act);

    k_zero<<<1, 64>>>();
    k_gate<<<T, 64>>>(x, gw, gb);
    k_scan<<<1, 32>>>();

    // shared expert MLP (tf32 tensor cores)
    k_mm<0><<<dim3(SHINTER / 64, T / 128), 256>>>(x,  wup, h1,  HIDDEN,  SHINTER);
    k_mm<1><<<dim3(HIDDEN  / 64, T / 128), 256>>>(h1, wdn, out, SHINTER, HIDDEN);
    // routed experts
    k_mm<2><<<dim3(INTER  / 64, NEXP), 256>>>(x,   w1, act, HIDDEN, INTER);
    k_mm<3><<<dim3(HIDDEN / 64, NEXP), 256>>>(act, w2, out, INTER,  HIDDEN);
}

// round 5
// speedup vs baseline: 5.1749x; 1.1707x over previous
#include <cuda_runtime.h>
#include <math.h>
#include <stdint.h>

#define HIDDEN   2048
#define NEXP     64
#define TOPK     6
#define NGRP     8
#define EPG      8
#define TOPKG    4
#define INTER    1024
#define SHINTER  4096
#define RSCALE   2.5f
#define MAXT     1024
#define ACT_ROWS 14336

#define ASTR 36               // A smem row stride (u32), frag bank = 4*grp+tg
#define BSTR 136              // B smem row stride (u32), frag bank = 8*tg+grp
#define ASZ  (128 * ASTR)     // per-buffer A tile
#define BSZ  (32 * BSTR)      // per-buffer B tile
#define SMEM_BYTES ((2 * ASZ + 2 * BSZ + 256) * 4)

// ---------------- scratch ---------------------------------------------------
__device__ int   g_cnt[NEXP];
__device__ int   g_off[NEXP];
__device__ int   g_tok[NEXP * MAXT];
__device__ float g_wt [NEXP * MAXT];
__device__ float g_h1 [MAXT * SHINTER];
__device__ float g_act[(size_t)ACT_ROWS * INTER];

__global__ void k_zero() {
    if (threadIdx.x < NEXP) g_cnt[threadIdx.x] = 0;
}
__global__ void k_scan() {
    if (threadIdx.x == 0) {
        int acc = 0;
        for (int e = 0; e < NEXP; e++) {
            g_off[e] = acc;
            acc += (g_cnt[e] + 127) & ~127;
        }
    }
}

// ---------------- gating ----------------------------------------------------
__global__ void k_gate(const float* __restrict__ x,
                       const float* __restrict__ gw,
                       const float* __restrict__ gb) {
    __shared__ float xs[HIDDEN];
    __shared__ float sc[NEXP];
    __shared__ float sb[NEXP];
    const int t = blockIdx.x;
    const float* xr = x + (size_t)t * HIDDEN;
    for (int i = threadIdx.x; i < HIDDEN / 4; i += blockDim.x)
        ((float4*)xs)[i] = ((const float4*)xr)[i];
    __syncthreads();

    {
        const int e = threadIdx.x;
        const float4* w4 = (const float4*)(gw + (size_t)e * HIDDEN);
        float acc = 0.f;
#pragma unroll 8
        for (int i = 0; i < HIDDEN / 4; i++) {
            float4 wv = w4[i];
            float4 xv = ((float4*)xs)[i];
            acc += wv.x * xv.x + wv.y * xv.y + wv.z * xv.z + wv.w * xv.w;
        }
        float s = 1.f / (1.f + expf(-acc));
        sc[e] = s;
        sb[e] = s + gb[e];
    }
    __syncthreads();

    if (threadIdx.x == 0) {
        float gs[NGRP];
        for (int g = 0; g < NGRP; g++) {
            float m1 = -1e30f, m2 = -1e30f;
            for (int j = 0; j < EPG; j++) {
                float v = sb[g * EPG + j];
                if (v > m1) { m2 = m1; m1 = v; }
                else if (v > m2) { m2 = v; }
            }
            gs[g] = m1 + m2;
        }
        bool gsel[NGRP];
        for (int g = 0; g < NGRP; g++) gsel[g] = false;
        for (int r = 0; r < TOPKG; r++) {
            int bi = -1; float bv = -1e30f;
            for (int g = 0; g < NGRP; g++)
                if (!gsel[g] && gs[g] > bv) { bv = gs[g]; bi = g; }
            gsel[bi] = true;
        }
        bool esel[NEXP];
        for (int e = 0; e < NEXP; e++) esel[e] = false;
        int   eidx[TOPK];
        float wv[TOPK];
        float wsum = 0.f;
        for (int r = 0; r < TOPK; r++) {
            int bi = -1; float bv = -INFINITY;
            for (int e = 0; e < NEXP; e++) {
                if (!gsel[e / EPG] || esel[e]) continue;
                if (sb[e] > bv) { bv = sb[e]; bi = e; }
            }
            esel[bi] = true;
            eidx[r] = bi;
            wv[r] = sc[bi];
            wsum += sc[bi];
        }
        float inv = RSCALE / (wsum + 1e-20f);
        for (int r = 0; r < TOPK; r++) {
            int e = eidx[r];
            int p = atomicAdd(&g_cnt[e], 1);
            g_tok[e * MAXT + p] = t;
            g_wt [e * MAXT + p] = wv[r] * inv;
        }
    }
}

// ---------------- tf32 helpers ----------------------------------------------
__device__ __forceinline__ uint32_t f2tf(float x) {
    uint32_t u;
    asm("cvt.rna.tf32.f32 %0, %1;" : "=r"(u) : "f"(x));
    return u;
}
__device__ __forceinline__ void mma8(float4& d, const uint32_t a[4],
                                     uint32_t b0, uint32_t b1) {
    asm("mma.sync.aligned.m16n8k8.row.col.f32.tf32.tf32.f32 "
        "{%0,%1,%2,%3},{%4,%5,%6,%7},{%8,%9},{%0,%1,%2,%3};"
        : "+f"(d.x), "+f"(d.y), "+f"(d.z), "+f"(d.w)
        : "r"(a[0]), "r"(a[1]), "r"(a[2]), "r"(a[3]), "r"(b0), "r"(b1));
}

// ---------------- tf32 GEMM: BM=128 BN=128 BK=32, 256 thr, warp 32x64 -------
// smem holds tf32-converted operands; register-staged double buffering.
// MODE 0: shared-up   h1 = relu2(x@wup)
// MODE 1: shared-down out = h1@wdn
// MODE 2: routed-up   g_act = relu2(Xg@w1[e]) * route_w
// MODE 3: routed-down out += g_act[e]@w2[e]   (atomic scatter)
template <int MODE>
__global__ __launch_bounds__(256) void k_mm(const float* __restrict__ A,
                                            const float* __restrict__ Bg,
                                            float* __restrict__ C,
                                            int K, int N) {
    extern __shared__ uint32_t sm[];
    uint32_t* As = sm;                       // [2][ASZ]
    uint32_t* Bs = sm + 2 * ASZ;             // [2][BSZ]
    int*   stok = (int*)(sm + 2 * ASZ + 2 * BSZ);
    float* swt  = (float*)(stok + 128);

    const int tid  = threadIdx.x;
    const int lane = tid & 31;
    const int warp = tid >> 5;
    const int wm   = warp & 3;               // 4 warps along M
    const int wn   = warp >> 2;              // 2 warps along N
    const int grp  = lane >> 2;
    const int tg   = lane & 3;
    const int n0   = blockIdx.x * 128;

    const int arow = tid >> 3;               // 0..31 (4 rows, +32*i)
    const int acol = (tid & 7) * 4;
    const int brow = tid >> 5;               // warp-id row (+8*i)
    const int bcol = (tid & 31) * 4;

    int e = 0, cnt = 0, m_begin, m_end;
    const float* B = Bg;
    const float* Abase = A;
    if (MODE <= 1) {
        m_begin = blockIdx.y * 128;
        m_end   = m_begin + 128;
    } else {
        e   = blockIdx.y;
        cnt = g_cnt[e];
        if (cnt == 0) return;
        m_begin = 0;
        m_end   = (cnt + 127) & ~127;
        B = Bg + (size_t)e * K * N;
        if (MODE == 3) Abase = A + (size_t)g_off[e] * K;
    }

    for (int m0 = m_begin; m0 < m_end; m0 += 128) {
        if (MODE >= 2) {
            __syncthreads();
            if (tid < 128) {
                int r = m0 + tid;
                int valid = r < cnt;
                stok[tid] = g_tok[e * MAXT + (valid ? r : 0)];
                swt [tid] = valid ? g_wt[e * MAXT + r] : 0.f;
            }
            __syncthreads();
        }

        const float* aptr[4];
#pragma unroll
        for (int i = 0; i < 4; i++) {
            int r = arow + 32 * i;
            if (MODE == 2)      aptr[i] = A + (size_t)stok[r] * K + acol;
            else if (MODE == 3) aptr[i] = Abase + (size_t)(m0 + r) * K + acol;
            else                aptr[i] = A + (size_t)(m0 + r) * K + acol;
        }
        const float* bptr = B + (size_t)brow * N + n0 + bcol;

        float4 acc[2][8];
#pragma unroll
        for (int i = 0; i < 2; i++)
#pragma unroll
            for (int j = 0; j < 8; j++) acc[i][j] = make_float4(0.f, 0.f, 0.f, 0.f);

        float4 ar[4], br[4];
        // prologue: tile 0
#pragma unroll
        for (int i = 0; i < 4; i++) ar[i] = *(const float4*)(aptr[i]);
#pragma unroll
        for (int i = 0; i < 4; i++) br[i] = *(const float4*)(bptr + (size_t)(8 * i) * N);
        {
            uint32_t* ab = As;
            uint32_t* bb = Bs;
#pragma unroll
            for (int i = 0; i < 4; i++) {
                uint32_t* p = ab + (arow + 32 * i) * ASTR + acol;
                p[0] = f2tf(ar[i].x); p[1] = f2tf(ar[i].y);
                p[2] = f2tf(ar[i].z); p[3] = f2tf(ar[i].w);
            }
#pragma unroll
            for (int i = 0; i < 4; i++) {
                uint32_t* p = bb + (brow + 8 * i) * BSTR + bcol;
                p[0] = f2tf(br[i].x); p[1] = f2tf(br[i].y);
                p[2] = f2tf(br[i].z); p[3] = f2tf(br[i].w);
            }
        }
        __syncthreads();

        const int NK = K / 32;
        for (int kt = 0; kt < NK; kt++) {
            const int cur = kt & 1;
            const bool more = (kt + 1) < NK;
            if (more) {
                int k0 = (kt + 1) * 32;
#pragma unroll
                for (int i = 0; i < 4; i++) ar[i] = *(const float4*)(aptr[i] + k0);
#pragma unroll
                for (int i = 0; i < 4; i++)
                    br[i] = *(const float4*)(bptr + (size_t)(k0 + 8 * i) * N);
            }
            // compute current buffer
            {
                const uint32_t* ab = As + cur * ASZ;
                const uint32_t* bb = Bs + cur * BSZ;
#pragma unroll
                for (int kk = 0; kk < 32; kk += 8) {
                    uint32_t af[2][4];
#pragma unroll
                    for (int mt = 0; mt < 2; mt++) {
                        int rb = (wm * 32 + mt * 16 + grp) * ASTR + kk;
                        af[mt][0] = ab[rb + tg];
                        af[mt][1] = ab[rb + 8 * ASTR + tg];
                        af[mt][2] = ab[rb + tg + 4];
                        af[mt][3] = ab[rb + 8 * ASTR + tg + 4];
                    }
#pragma unroll
                    for (int nt = 0; nt < 8; nt++) {
                        int cb = (kk + tg) * BSTR + wn * 64 + nt * 8 + grp;
                        uint32_t b0 = bb[cb];
                        uint32_t b1 = bb[cb + 4 * BSTR];
                        mma8(acc[0][nt], af[0], b0, b1);
                        mma8(acc[1][nt], af[1], b0, b1);
                    }
                }
            }
            if (more) {
                uint32_t* ab = As + (cur ^ 1) * ASZ;
                uint32_t* bb = Bs + (cur ^ 1) * BSZ;
#pragma unroll
                for (int i = 0; i < 4; i++) {
                    uint32_t* p = ab + (arow + 32 * i) * ASTR + acol;
                    p[0] = f2tf(ar[i].x); p[1] = f2tf(ar[i].y);
                    p[2] = f2tf(ar[i].z); p[3] = f2tf(ar[i].w);
                }
#pragma unroll
                for (int i = 0; i < 4; i++) {
                    uint32_t* p = bb + (brow + 8 * i) * BSTR + bcol;
                    p[0] = f2tf(br[i].x); p[1] = f2tf(br[i].y);
                    p[2] = f2tf(br[i].z); p[3] = f2tf(br[i].w);
                }
            }
            __syncthreads();
        }

        // epilogue
#pragma unroll
        for (int mt = 0; mt < 2; mt++) {
            int r0 = wm * 32 + mt * 16 + grp;
            int r1 = r0 + 8;
#pragma unroll
            for (int nt = 0; nt < 8; nt++) {
                int c = n0 + wn * 64 + nt * 8 + tg * 2;
                float4 v = acc[mt][nt];
                if (MODE == 0 || MODE == 2) {
                    v.x = fmaxf(v.x, 0.f); v.x *= v.x;
                    v.y = fmaxf(v.y, 0.f); v.y *= v.y;
                    v.z = fmaxf(v.z, 0.f); v.z *= v.z;
                    v.w = fmaxf(v.w, 0.f); v.w *= v.w;
                }
                if (MODE == 2) {
                    float w0 = swt[r0], w1 = swt[r1];
                    v.x *= w0; v.y *= w0; v.z *= w1; v.w *= w1;
                }
                if (MODE == 3) {
                    if (m0 + r0 < cnt) {
                        float* o = C + (size_t)stok[r0] * N + c;
                        atomicAdd(o, v.x);
                        atomicAdd(o + 1, v.y);
                    }
                    if (m0 + r1 < cnt) {
                        float* o = C + (size_t)stok[r1] * N + c;
                        atomicAdd(o, v.z);
                        atomicAdd(o + 1, v.w);
                    }
                } else if (MODE == 2) {
                    float* crow = C + (size_t)(g_off[e] + m0 + r0) * N + c;
                    *(float2*)crow = make_float2(v.x, v.y);
                    crow = C + (size_t)(g_off[e] + m0 + r1) * N + c;
                    *(float2*)crow = make_float2(v.z, v.w);
                } else {
                    *(float2*)(C + (size_t)(m0 + r0) * N + c) = make_float2(v.x, v.y);
                    *(float2*)(C + (size_t)(m0 + r1) * N + c) = make_float2(v.z, v.w);
                }
            }
        }
    }
}

// ---------------------------------------------------------------------------
extern "C" void kernel_launch(void* const* d_in, const int* in_sizes, int n_in,
                              void* d_out, int out_size) {
    const float* x   = (const float*)d_in[0];
    const float* gw  = (const float*)d_in[1];
    const float* gb  = (const float*)d_in[2];
    const float* wup = (const float*)d_in[3];
    const float* wdn = (const float*)d_in[4];
    const float* w1  = (const float*)d_in[5];
    const float* w2  = (const float*)d_in[6];
    float* out = (float*)d_out;

    const int T = in_sizes[0] / HIDDEN;      // 1024

    float* h1 = nullptr;
    cudaGetSymbolAddress((void**)&h1, g_h1);
    float* act = nullptr;
    cudaGetSymbolAddress((void**)&act, g_act);

    // unconditional (no static guards allowed); host-side, capture-legal
    cudaFuncSetAttribute(k_mm<0>, cudaFuncAttributeMaxDynamicSharedMemorySize, SMEM_BYTES);
    cudaFuncSetAttribute(k_mm<1>, cudaFuncAttributeMaxDynamicSharedMemorySize, SMEM_BYTES);
    cudaFuncSetAttribute(k_mm<2>, cudaFuncAttributeMaxDynamicSharedMemorySize, SMEM_BYTES);
    cudaFuncSetAttribute(k_mm<3>, cudaFuncAttributeMaxDynamicSharedMemorySize, SMEM_BYTES);

    k_zero<<<1, 64>>>();
    k_gate<<<T, 64>>>(x, gw, gb);
    k_scan<<<1, 32>>>();

    k_mm<0><<<dim3(SHINTER / 128, T / 128), 256, SMEM_BYTES>>>(x,  wup, h1,  HIDDEN,  SHINTER);
    k_mm<1><<<dim3(HIDDEN  / 128, T / 128), 256, SMEM_BYTES>>>(h1, wdn, out, SHINTER, HIDDEN);
    k_mm<2><<<dim3(INTER  / 128, NEXP), 256, SMEM_BYTES>>>(x,   w1, act, HIDDEN, INTER);
    k_mm<3><<<dim3(HIDDEN / 128, NEXP), 256, SMEM_BYTES>>>(act, w2, out, INTER,  HIDDEN);
}

// round 6
// speedup vs baseline: 5.4582x; 1.0547x over previous
#include <cuda_runtime.h>
#include <math.h>
#include <stdint.h>

#define HIDDEN   2048
#define NEXP     64
#define TOPK     6
#define NGRP     8
#define EPG      8
#define TOPKG    4
#define INTER    1024
#define SHINTER  4096
#define RSCALE   2.5f
#define MAXT     1024
#define ACT_ROWS 14336

#define ASTR 36               // A smem row stride (u32), frag bank = 4*grp+tg
#define BSTR 136              // B smem row stride (u32), frag bank = 8*tg+grp
#define ASZ  (128 * ASTR)     // per-buffer A tile
#define BSZ  (32 * BSTR)      // per-buffer B tile
#define SMEM_BYTES ((2 * ASZ + 2 * BSZ + 256) * 4)

// ---------------- scratch ---------------------------------------------------
__device__ int   g_cnt[NEXP];
__device__ int   g_off[NEXP];
__device__ int   g_tok[NEXP * MAXT];
__device__ float g_wt [NEXP * MAXT];
__device__ float g_h1 [MAXT * SHINTER];
__device__ float g_act[(size_t)ACT_ROWS * INTER];

__global__ void k_zero() {
    if (threadIdx.x < NEXP) g_cnt[threadIdx.x] = 0;
}
__global__ void k_scan() {
    if (threadIdx.x == 0) {
        int acc = 0;
        for (int e = 0; e < NEXP; e++) {
            g_off[e] = acc;
            acc += (g_cnt[e] + 127) & ~127;
        }
    }
}

// ---------------- gating ----------------------------------------------------
__global__ void k_gate(const float* __restrict__ x,
                       const float* __restrict__ gw,
                       const float* __restrict__ gb) {
    __shared__ float xs[HIDDEN];
    __shared__ float sc[NEXP];
    __shared__ float sb[NEXP];
    const int t = blockIdx.x;
    const float* xr = x + (size_t)t * HIDDEN;
    for (int i = threadIdx.x; i < HIDDEN / 4; i += blockDim.x)
        ((float4*)xs)[i] = ((const float4*)xr)[i];
    __syncthreads();

    {
        const int e = threadIdx.x;
        const float4* w4 = (const float4*)(gw + (size_t)e * HIDDEN);
        float acc = 0.f;
#pragma unroll 8
        for (int i = 0; i < HIDDEN / 4; i++) {
            float4 wv = w4[i];
            float4 xv = ((float4*)xs)[i];
            acc += wv.x * xv.x + wv.y * xv.y + wv.z * xv.z + wv.w * xv.w;
        }
        float s = 1.f / (1.f + expf(-acc));
        sc[e] = s;
        sb[e] = s + gb[e];
    }
    __syncthreads();

    if (threadIdx.x == 0) {
        float gs[NGRP];
        for (int g = 0; g < NGRP; g++) {
            float m1 = -1e30f, m2 = -1e30f;
            for (int j = 0; j < EPG; j++) {
                float v = sb[g * EPG + j];
                if (v > m1) { m2 = m1; m1 = v; }
                else if (v > m2) { m2 = v; }
            }
            gs[g] = m1 + m2;
        }
        bool gsel[NGRP];
        for (int g = 0; g < NGRP; g++) gsel[g] = false;
        for (int r = 0; r < TOPKG; r++) {
            int bi = -1; float bv = -1e30f;
            for (int g = 0; g < NGRP; g++)
                if (!gsel[g] && gs[g] > bv) { bv = gs[g]; bi = g; }
            gsel[bi] = true;
        }
        bool esel[NEXP];
        for (int e = 0; e < NEXP; e++) esel[e] = false;
        int   eidx[TOPK];
        float wv[TOPK];
        float wsum = 0.f;
        for (int r = 0; r < TOPK; r++) {
            int bi = -1; float bv = -INFINITY;
            for (int e = 0; e < NEXP; e++) {
                if (!gsel[e / EPG] || esel[e]) continue;
                if (sb[e] > bv) { bv = sb[e]; bi = e; }
            }
            esel[bi] = true;
            eidx[r] = bi;
            wv[r] = sc[bi];
            wsum += sc[bi];
        }
        float inv = RSCALE / (wsum + 1e-20f);
        for (int r = 0; r < TOPK; r++) {
            int e = eidx[r];
            int p = atomicAdd(&g_cnt[e], 1);
            g_tok[e * MAXT + p] = t;
            g_wt [e * MAXT + p] = wv[r] * inv;
        }
    }
}

// ---------------- tf32 helpers ----------------------------------------------
__device__ __forceinline__ uint32_t f2tf(float x) {
    uint32_t u;
    asm("cvt.rna.tf32.f32 %0, %1;" : "=r"(u) : "f"(x));
    return u;
}
__device__ __forceinline__ void mma8(float4& d, const uint32_t a[4],
                                     uint32_t b0, uint32_t b1) {
    asm("mma.sync.aligned.m16n8k8.row.col.f32.tf32.tf32.f32 "
        "{%0,%1,%2,%3},{%4,%5,%6,%7},{%8,%9},{%0,%1,%2,%3};"
        : "+f"(d.x), "+f"(d.y), "+f"(d.z), "+f"(d.w)
        : "r"(a[0]), "r"(a[1]), "r"(a[2]), "r"(a[3]), "r"(b0), "r"(b1));
}

// ---------------- tf32 GEMM: BM=128 BN=128 BK=32, 256 thr, warp 32x64 -------
// smem holds tf32-converted operands; register-staged double buffering.
// __launch_bounds__(256,2): cap regs at 128 so 2 CTAs/SM fit (occupancy fix).
// MODE 0: shared-up   h1 = relu2(x@wup)
// MODE 1: shared-down out = h1@wdn
// MODE 2: routed-up   g_act = relu2(Xg@w1[e]) * route_w
// MODE 3: routed-down out += g_act[e]@w2[e]   (atomic scatter)
template <int MODE>
__global__ __launch_bounds__(256, 2) void k_mm(const float* __restrict__ A,
                                               const float* __restrict__ Bg,
                                               float* __restrict__ C,
                                               int K, int N) {
    extern __shared__ uint32_t sm[];
    uint32_t* As = sm;                       // [2][ASZ]
    uint32_t* Bs = sm + 2 * ASZ;             // [2][BSZ]
    int*   stok = (int*)(sm + 2 * ASZ + 2 * BSZ);
    float* swt  = (float*)(stok + 128);

    const int tid  = threadIdx.x;
    const int lane = tid & 31;
    const int warp = tid >> 5;
    const int wm   = warp & 3;               // 4 warps along M
    const int wn   = warp >> 2;              // 2 warps along N
    const int grp  = lane >> 2;
    const int tg   = lane & 3;
    const int n0   = blockIdx.x * 128;

    const int arow = tid >> 3;               // 0..31 (4 rows, +32*i)
    const int acol = (tid & 7) * 4;
    const int brow = tid >> 5;               // warp-id row (+8*i)
    const int bcol = (tid & 31) * 4;

    int e = 0, cnt = 0, m_begin, m_end;
    const float* B = Bg;
    const float* Abase = A;
    if (MODE <= 1) {
        m_begin = blockIdx.y * 128;
        m_end   = m_begin + 128;
    } else {
        e   = blockIdx.y;
        cnt = g_cnt[e];
        if (cnt == 0) return;
        m_begin = 0;
        m_end   = (cnt + 127) & ~127;
        B = Bg + (size_t)e * K * N;
        if (MODE == 3) Abase = A + (size_t)g_off[e] * K;
    }

    for (int m0 = m_begin; m0 < m_end; m0 += 128) {
        if (MODE >= 2) {
            __syncthreads();
            if (tid < 128) {
                int r = m0 + tid;
                int valid = r < cnt;
                stok[tid] = g_tok[e * MAXT + (valid ? r : 0)];
                swt [tid] = valid ? g_wt[e * MAXT + r] : 0.f;
            }
            __syncthreads();
        }

        // 32-bit row offsets off one base pointer (saves regs vs 4 pointers)
        uint32_t aofs[4];
#pragma unroll
        for (int i = 0; i < 4; i++) {
            int r = arow + 32 * i;
            if (MODE == 2)      aofs[i] = (uint32_t)stok[r] * (uint32_t)K + acol;
            else                aofs[i] = (uint32_t)(m0 + r) * (uint32_t)K + acol;
        }
        const float* abase = (MODE == 3) ? Abase : ((MODE == 2) ? A : A);
        const float* bptr = B + (size_t)brow * N + n0 + bcol;

        float4 acc[2][8];
#pragma unroll
        for (int i = 0; i < 2; i++)
#pragma unroll
            for (int j = 0; j < 8; j++) acc[i][j] = make_float4(0.f, 0.f, 0.f, 0.f);

        float4 ar[4], br[4];
        // prologue: tile 0
#pragma unroll
        for (int i = 0; i < 4; i++) ar[i] = *(const float4*)(abase + aofs[i]);
#pragma unroll
        for (int i = 0; i < 4; i++) br[i] = *(const float4*)(bptr + (size_t)(8 * i) * N);
        {
            uint32_t* ab = As;
            uint32_t* bb = Bs;
#pragma unroll
            for (int i = 0; i < 4; i++) {
                uint32_t* p = ab + (arow + 32 * i) * ASTR + acol;
                p[0] = f2tf(ar[i].x); p[1] = f2tf(ar[i].y);
                p[2] = f2tf(ar[i].z); p[3] = f2tf(ar[i].w);
            }
#pragma unroll
            for (int i = 0; i < 4; i++) {
                uint32_t* p = bb + (brow + 8 * i) * BSTR + bcol;
                p[0] = f2tf(br[i].x); p[1] = f2tf(br[i].y);
                p[2] = f2tf(br[i].z); p[3] = f2tf(br[i].w);
            }
        }
        __syncthreads();

        const int NK = K / 32;
        for (int kt = 0; kt < NK; kt++) {
            const int cur = kt & 1;
            const bool more = (kt + 1) < NK;
            if (more) {
                int k0 = (kt + 1) * 32;
#pragma unroll
                for (int i = 0; i < 4; i++)
                    ar[i] = *(const float4*)(abase + aofs[i] + k0);
#pragma unroll
                for (int i = 0; i < 4; i++)
                    br[i] = *(const float4*)(bptr + (size_t)(k0 + 8 * i) * N);
            }
            // compute current buffer
            {
                const uint32_t* ab = As + cur * ASZ;
                const uint32_t* bb = Bs + cur * BSZ;
#pragma unroll
                for (int kk = 0; kk < 32; kk += 8) {
                    uint32_t af[2][4];
#pragma unroll
                    for (int mt = 0; mt < 2; mt++) {
                        int rb = (wm * 32 + mt * 16 + grp) * ASTR + kk;
                        af[mt][0] = ab[rb + tg];
                        af[mt][1] = ab[rb + 8 * ASTR + tg];
                        af[mt][2] = ab[rb + tg + 4];
                        af[mt][3] = ab[rb + 8 * ASTR + tg + 4];
                    }
#pragma unroll
                    for (int nt = 0; nt < 8; nt++) {
                        int cb = (kk + tg) * BSTR + wn * 64 + nt * 8 + grp;
                        uint32_t b0 = bb[cb];
                        uint32_t b1 = bb[cb + 4 * BSTR];
                        mma8(acc[0][nt], af[0], b0, b1);
                        mma8(acc[1][nt], af[1], b0, b1);
                    }
                }
            }
            if (more) {
                uint32_t* ab = As + (cur ^ 1) * ASZ;
                uint32_t* bb = Bs + (cur ^ 1) * BSZ;
#pragma unroll
                for (int i = 0; i < 4; i++) {
                    uint32_t* p = ab + (arow + 32 * i) * ASTR + acol;
                    p[0] = f2tf(ar[i].x); p[1] = f2tf(ar[i].y);
                    p[2] = f2tf(ar[i].z); p[3] = f2tf(ar[i].w);
                }
#pragma unroll
                for (int i = 0; i < 4; i++) {
                    uint32_t* p = bb + (brow + 8 * i) * BSTR + bcol;
                    p[0] = f2tf(br[i].x); p[1] = f2tf(br[i].y);
                    p[2] = f2tf(br[i].z); p[3] = f2tf(br[i].w);
                }
            }
            __syncthreads();
        }

        // epilogue
#pragma unroll
        for (int mt = 0; mt < 2; mt++) {
            int r0 = wm * 32 + mt * 16 + grp;
            int r1 = r0 + 8;
#pragma unroll
            for (int nt = 0; nt < 8; nt++) {
                int c = n0 + wn * 64 + nt * 8 + tg * 2;
                float4 v = acc[mt][nt];
                if (MODE == 0 || MODE == 2) {
                    v.x = fmaxf(v.x, 0.f); v.x *= v.x;
                    v.y = fmaxf(v.y, 0.f); v.y *= v.y;
                    v.z = fmaxf(v.z, 0.f); v.z *= v.z;
                    v.w = fmaxf(v.w, 0.f); v.w *= v.w;
                }
                if (MODE == 2) {
                    float w0 = swt[r0], w1 = swt[r1];
                    v.x *= w0; v.y *= w0; v.z *= w1; v.w *= w1;
                }
                if (MODE == 3) {
                    if (m0 + r0 < cnt) {
                        float* o = C + (size_t)stok[r0] * N + c;
                        atomicAdd(o, v.x);
                        atomicAdd(o + 1, v.y);
                    }
                    if (m0 + r1 < cnt) {
                        float* o = C + (size_t)stok[r1] * N + c;
                        atomicAdd(o, v.z);
                        atomicAdd(o + 1, v.w);
                    }
                } else if (MODE == 2) {
                    float* crow = C + (size_t)(g_off[e] + m0 + r0) * N + c;
                    *(float2*)crow = make_float2(v.x, v.y);
                    crow = C + (size_t)(g_off[e] + m0 + r1) * N + c;
                    *(float2*)crow = make_float2(v.z, v.w);
                } else {
                    *(float2*)(C + (size_t)(m0 + r0) * N + c) = make_float2(v.x, v.y);
                    *(float2*)(C + (size_t)(m0 + r1) * N + c) = make_float2(v.z, v.w);
                }
            }
        }
    }
}

// ---------------------------------------------------------------------------
extern "C" void kernel_launch(void* const* d_in, const int* in_sizes, int n_in,
                              void* d_out, int out_size) {
    const float* x   = (const float*)d_in[0];
    const float* gw  = (const float*)d_in[1];
    const float* gb  = (const float*)d_in[2];
    const float* wup = (const float*)d_in[3];
    const float* wdn = (const float*)d_in[4];
    const float* w1  = (const float*)d_in[5];
    const float* w2  = (const float*)d_in[6];
    float* out = (float*)d_out;

    const int T = in_sizes[0] / HIDDEN;      // 1024

    float* h1 = nullptr;
    cudaGetSymbolAddress((void**)&h1, g_h1);
    float* act = nullptr;
    cudaGetSymbolAddress((void**)&act, g_act);

    // unconditional (no static guards allowed); host-side, capture-legal
    cudaFuncSetAttribute(k_mm<0>, cudaFuncAttributeMaxDynamicSharedMemorySize, SMEM_BYTES);
    cudaFuncSetAttribute(k_mm<1>, cudaFuncAttributeMaxDynamicSharedMemorySize, SMEM_BYTES);
    cudaFuncSetAttribute(k_mm<2>, cudaFuncAttributeMaxDynamicSharedMemorySize, SMEM_BYTES);
    cudaFuncSetAttribute(k_mm<3>, cudaFuncAttributeMaxDynamicSharedMemorySize, SMEM_BYTES);

    k_zero<<<1, 64>>>();
    k_gate<<<T, 64>>>(x, gw, gb);
    k_scan<<<1, 32>>>();

    k_mm<0><<<dim3(SHINTER / 128, T / 128), 256, SMEM_BYTES>>>(x,  wup, h1,  HIDDEN,  SHINTER);
    k_mm<1><<<dim3(HIDDEN  / 128, T / 128), 256, SMEM_BYTES>>>(h1, wdn, out, SHINTER, HIDDEN);
    k_mm<2><<<dim3(INTER  / 128, NEXP), 256, SMEM_BYTES>>>(x,   w1, act, HIDDEN, INTER);
    k_mm<3><<<dim3(HIDDEN / 128, NEXP), 256, SMEM_BYTES>>>(act, w2, out, INTER,  HIDDEN);
}

// round 7
// speedup vs baseline: 5.9781x; 1.0953x over previous
#include <cuda_runtime.h>
#include <math.h>
#include <stdint.h>

#define HIDDEN   2048
#define NEXP     64
#define TOPK     6
#define NGRP     8
#define EPG      8
#define TOPKG    4
#define INTER    1024
#define SHINTER  4096
#define RSCALE   2.5f
#define MAXT     1024
#define ACT_ROWS 14336

#define ASTR 36               // A smem row stride (u32), frag bank = 4*grp+tg
#define BSTR 136              // B smem row stride (u32), frag bank = 8*tg+grp
#define ASZ  (128 * ASTR)     // per-buffer A tile
#define BSZ  (32 * BSTR)      // per-buffer B tile
#define SMEM_BYTES ((2 * ASZ + 2 * BSZ + 256) * 4)

// fused-kernel CTA counts
#define NB_M0  ((SHINTER / 128) * (MAXT / 128))   // 32*8  = 256
#define NB_M2  ((INTER / 128) * NEXP)             // 8*64  = 512
#define NB_M1  ((HIDDEN / 128) * (MAXT / 128))    // 16*8  = 128
#define NB_M3  ((HIDDEN / 128) * NEXP)            // 16*64 = 1024

// ---------------- scratch ---------------------------------------------------
__device__ int   g_cnt[NEXP];
__device__ int   g_off[NEXP];
__device__ int   g_tok[NEXP * MAXT];
__device__ float g_wt [NEXP * MAXT];
__device__ float g_h1 [MAXT * SHINTER];
__device__ float g_act[(size_t)ACT_ROWS * INTER];

__global__ void k_zero() {
    if (threadIdx.x < NEXP) g_cnt[threadIdx.x] = 0;
}
__global__ void k_scan() {
    if (threadIdx.x == 0) {
        int acc = 0;
        for (int e = 0; e < NEXP; e++) {
            g_off[e] = acc;
            acc += (g_cnt[e] + 127) & ~127;
        }
    }
}

// ---------------- gating ----------------------------------------------------
__global__ void k_gate(const float* __restrict__ x,
                       const float* __restrict__ gw,
                       const float* __restrict__ gb) {
    __shared__ float xs[HIDDEN];
    __shared__ float sc[NEXP];
    __shared__ float sb[NEXP];
    const int t = blockIdx.x;
    const float* xr = x + (size_t)t * HIDDEN;
    for (int i = threadIdx.x; i < HIDDEN / 4; i += blockDim.x)
        ((float4*)xs)[i] = ((const float4*)xr)[i];
    __syncthreads();

    {
        const int e = threadIdx.x;
        const float4* w4 = (const float4*)(gw + (size_t)e * HIDDEN);
        float acc = 0.f;
#pragma unroll 8
        for (int i = 0; i < HIDDEN / 4; i++) {
            float4 wv = w4[i];
            float4 xv = ((float4*)xs)[i];
            acc += wv.x * xv.x + wv.y * xv.y + wv.z * xv.z + wv.w * xv.w;
        }
        float s = 1.f / (1.f + expf(-acc));
        sc[e] = s;
        sb[e] = s + gb[e];
    }
    __syncthreads();

    if (threadIdx.x == 0) {
        float gs[NGRP];
        for (int g = 0; g < NGRP; g++) {
            float m1 = -1e30f, m2 = -1e30f;
            for (int j = 0; j < EPG; j++) {
                float v = sb[g * EPG + j];
                if (v > m1) { m2 = m1; m1 = v; }
                else if (v > m2) { m2 = v; }
            }
            gs[g] = m1 + m2;
        }
        bool gsel[NGRP];
        for (int g = 0; g < NGRP; g++) gsel[g] = false;
        for (int r = 0; r < TOPKG; r++) {
            int bi = -1; float bv = -1e30f;
            for (int g = 0; g < NGRP; g++)
                if (!gsel[g] && gs[g] > bv) { bv = gs[g]; bi = g; }
            gsel[bi] = true;
        }
        bool esel[NEXP];
        for (int e = 0; e < NEXP; e++) esel[e] = false;
        int   eidx[TOPK];
        float wv[TOPK];
        float wsum = 0.f;
        for (int r = 0; r < TOPK; r++) {
            int bi = -1; float bv = -INFINITY;
            for (int e = 0; e < NEXP; e++) {
                if (!gsel[e / EPG] || esel[e]) continue;
                if (sb[e] > bv) { bv = sb[e]; bi = e; }
            }
            esel[bi] = true;
            eidx[r] = bi;
            wv[r] = sc[bi];
            wsum += sc[bi];
        }
        float inv = RSCALE / (wsum + 1e-20f);
        for (int r = 0; r < TOPK; r++) {
            int e = eidx[r];
            int p = atomicAdd(&g_cnt[e], 1);
            g_tok[e * MAXT + p] = t;
            g_wt [e * MAXT + p] = wv[r] * inv;
        }
    }
}

// ---------------- tf32 helpers ----------------------------------------------
__device__ __forceinline__ uint32_t f2tf(float x) {
    uint32_t u;
    asm("cvt.rna.tf32.f32 %0, %1;" : "=r"(u) : "f"(x));
    return u;
}
__device__ __forceinline__ void mma8(float4& d, const uint32_t a[4],
                                     uint32_t b0, uint32_t b1) {
    asm("mma.sync.aligned.m16n8k8.row.col.f32.tf32.tf32.f32 "
        "{%0,%1,%2,%3},{%4,%5,%6,%7},{%8,%9},{%0,%1,%2,%3};"
        : "+f"(d.x), "+f"(d.y), "+f"(d.z), "+f"(d.w)
        : "r"(a[0]), "r"(a[1]), "r"(a[2]), "r"(a[3]), "r"(b0), "r"(b1));
}

// ---------------- tf32 GEMM body: BM=128 BN=128 BK=32, 256 thr --------------
// MODE 0: h1 = relu2(x@wup)                 (plain store)
// MODE 1: out += h1@wdn                     (atomicAdd; out pre-zeroed)
// MODE 2: g_act = relu2(Xg@w1[e]) * route_w (gathered A, plain store)
// MODE 3: out += g_act[e]@w2[e]             (atomic scatter by token)
template <int MODE>
__device__ __forceinline__ void mm_body(int bx, int by,
                                        const float* __restrict__ A,
                                        const float* __restrict__ Bg,
                                        float* __restrict__ C,
                                        int K, int N) {
    extern __shared__ uint32_t sm[];
    uint32_t* As = sm;                       // [2][ASZ]
    uint32_t* Bs = sm + 2 * ASZ;             // [2][BSZ]
    int*   stok = (int*)(sm + 2 * ASZ + 2 * BSZ);
    float* swt  = (float*)(stok + 128);

    const int tid  = threadIdx.x;
    const int lane = tid & 31;
    const int warp = tid >> 5;
    const int wm   = warp & 3;
    const int wn   = warp >> 2;
    const int grp  = lane >> 2;
    const int tg   = lane & 3;
    const int n0   = bx * 128;

    const int arow = tid >> 3;
    const int acol = (tid & 7) * 4;
    const int brow = tid >> 5;
    const int bcol = (tid & 31) * 4;

    int e = 0, cnt = 0, m_begin, m_end;
    const float* B = Bg;
    const float* Abase = A;
    if (MODE == 0 || MODE == 1) {
        m_begin = by * 128;
        m_end   = m_begin + 128;
    } else {
        e   = by;
        cnt = g_cnt[e];
        if (cnt == 0) return;
        m_begin = 0;
        m_end   = (cnt + 127) & ~127;
        B = Bg + (size_t)e * K * N;
        if (MODE == 3) Abase = A + (size_t)g_off[e] * K;
    }

    for (int m0 = m_begin; m0 < m_end; m0 += 128) {
        if (MODE >= 2) {
            __syncthreads();
            if (tid < 128) {
                int r = m0 + tid;
                int valid = r < cnt;
                stok[tid] = g_tok[e * MAXT + (valid ? r : 0)];
                swt [tid] = valid ? g_wt[e * MAXT + r] : 0.f;
            }
            __syncthreads();
        }

        uint32_t aofs[4];
#pragma unroll
        for (int i = 0; i < 4; i++) {
            int r = arow + 32 * i;
            if (MODE == 2)      aofs[i] = (uint32_t)stok[r] * (uint32_t)K + acol;
            else                aofs[i] = (uint32_t)(m0 + r) * (uint32_t)K + acol;
        }
        const float* abase = Abase;
        const float* bptr = B + (size_t)brow * N + n0 + bcol;

        float4 acc[2][8];
#pragma unroll
        for (int i = 0; i < 2; i++)
#pragma unroll
            for (int j = 0; j < 8; j++) acc[i][j] = make_float4(0.f, 0.f, 0.f, 0.f);

        float4 ar[4], br[4];
#pragma unroll
        for (int i = 0; i < 4; i++) ar[i] = *(const float4*)(abase + aofs[i]);
#pragma unroll
        for (int i = 0; i < 4; i++) br[i] = *(const float4*)(bptr + (size_t)(8 * i) * N);
        {
            uint32_t* ab = As;
            uint32_t* bb = Bs;
#pragma unroll
            for (int i = 0; i < 4; i++) {
                uint32_t* p = ab + (arow + 32 * i) * ASTR + acol;
                p[0] = f2tf(ar[i].x); p[1] = f2tf(ar[i].y);
                p[2] = f2tf(ar[i].z); p[3] = f2tf(ar[i].w);
            }
#pragma unroll
            for (int i = 0; i < 4; i++) {
                uint32_t* p = bb + (brow + 8 * i) * BSTR + bcol;
                p[0] = f2tf(br[i].x); p[1] = f2tf(br[i].y);
                p[2] = f2tf(br[i].z); p[3] = f2tf(br[i].w);
            }
        }
        __syncthreads();

        const int NK = K / 32;
        for (int kt = 0; kt < NK; kt++) {
            const int cur = kt & 1;
            const bool more = (kt + 1) < NK;
            if (more) {
                int k0 = (kt + 1) * 32;
#pragma unroll
                for (int i = 0; i < 4; i++)
                    ar[i] = *(const float4*)(abase + aofs[i] + k0);
#pragma unroll
                for (int i = 0; i < 4; i++)
                    br[i] = *(const float4*)(bptr + (size_t)(k0 + 8 * i) * N);
            }
            {
                const uint32_t* ab = As + cur * ASZ;
                const uint32_t* bb = Bs + cur * BSZ;
#pragma unroll
                for (int kk = 0; kk < 32; kk += 8) {
                    uint32_t af[2][4];
#pragma unroll
                    for (int mt = 0; mt < 2; mt++) {
                        int rb = (wm * 32 + mt * 16 + grp) * ASTR + kk;
                        af[mt][0] = ab[rb + tg];
                        af[mt][1] = ab[rb + 8 * ASTR + tg];
                        af[mt][2] = ab[rb + tg + 4];
                        af[mt][3] = ab[rb + 8 * ASTR + tg + 4];
                    }
#pragma unroll
                    for (int nt = 0; nt < 8; nt++) {
                        int cb = (kk + tg) * BSTR + wn * 64 + nt * 8 + grp;
                        uint32_t b0 = bb[cb];
                        uint32_t b1 = bb[cb + 4 * BSTR];
                        mma8(acc[0][nt], af[0], b0, b1);
                        mma8(acc[1][nt], af[1], b0, b1);
                    }
                }
            }
            if (more) {
                uint32_t* ab = As + (cur ^ 1) * ASZ;
                uint32_t* bb = Bs + (cur ^ 1) * BSZ;
#pragma unroll
                for (int i = 0; i < 4; i++) {
                    uint32_t* p = ab + (arow + 32 * i) * ASTR + acol;
                    p[0] = f2tf(ar[i].x); p[1] = f2tf(ar[i].y);
                    p[2] = f2tf(ar[i].z); p[3] = f2tf(ar[i].w);
                }
#pragma unroll
                for (int i = 0; i < 4; i++) {
                    uint32_t* p = bb + (brow + 8 * i) * BSTR + bcol;
                    p[0] = f2tf(br[i].x); p[1] = f2tf(br[i].y);
                    p[2] = f2tf(br[i].z); p[3] = f2tf(br[i].w);
                }
            }
            __syncthreads();
        }

        // epilogue
#pragma unroll
        for (int mt = 0; mt < 2; mt++) {
            int r0 = wm * 32 + mt * 16 + grp;
            int r1 = r0 + 8;
#pragma unroll
            for (int nt = 0; nt < 8; nt++) {
                int c = n0 + wn * 64 + nt * 8 + tg * 2;
                float4 v = acc[mt][nt];
                if (MODE == 0 || MODE == 2) {
                    v.x = fmaxf(v.x, 0.f); v.x *= v.x;
                    v.y = fmaxf(v.y, 0.f); v.y *= v.y;
                    v.z = fmaxf(v.z, 0.f); v.z *= v.z;
                    v.w = fmaxf(v.w, 0.f); v.w *= v.w;
                }
                if (MODE == 2) {
                    float w0 = swt[r0], w1 = swt[r1];
                    v.x *= w0; v.y *= w0; v.z *= w1; v.w *= w1;
                }
                if (MODE == 3) {
                    if (m0 + r0 < cnt) {
                        float* o = C + (size_t)stok[r0] * N + c;
                        atomicAdd(o, v.x);
                        atomicAdd(o + 1, v.y);
                    }
                    if (m0 + r1 < cnt) {
                        float* o = C + (size_t)stok[r1] * N + c;
                        atomicAdd(o, v.z);
                        atomicAdd(o + 1, v.w);
                    }
                } else if (MODE == 1) {
                    float* o = C + (size_t)(m0 + r0) * N + c;
                    atomicAdd(o, v.x);
                    atomicAdd(o + 1, v.y);
                    o = C + (size_t)(m0 + r1) * N + c;
                    atomicAdd(o, v.z);
                    atomicAdd(o + 1, v.w);
                } else if (MODE == 2) {
                    float* crow = C + (size_t)(g_off[e] + m0 + r0) * N + c;
                    *(float2*)crow = make_float2(v.x, v.y);
                    crow = C + (size_t)(g_off[e] + m0 + r1) * N + c;
                    *(float2*)crow = make_float2(v.z, v.w);
                } else {
                    *(float2*)(C + (size_t)(m0 + r0) * N + c) = make_float2(v.x, v.y);
                    *(float2*)(C + (size_t)(m0 + r1) * N + c) = make_float2(v.z, v.w);
                }
            }
        }
    }
}

// ---- fused kernel A: mode0 (x->h1) + mode2 (x->g_act), independent ---------
__global__ __launch_bounds__(256, 2) void k_fuseA(const float* __restrict__ x,
                                                  const float* __restrict__ wup,
                                                  float* __restrict__ h1,
                                                  const float* __restrict__ w1,
                                                  float* __restrict__ act) {
    const int bid = blockIdx.x;
    if (bid < NB_M0) {
        mm_body<0>(bid % (SHINTER / 128), bid / (SHINTER / 128),
                   x, wup, h1, HIDDEN, SHINTER);
    } else {
        const int b = bid - NB_M0;
        mm_body<2>(b % (INTER / 128), b / (INTER / 128),
                   x, w1, act, HIDDEN, INTER);
    }
}

// ---- fused kernel B: mode1 (h1->out) + mode3 (act->out), both atomic -------
__global__ __launch_bounds__(256, 2) void k_fuseB(const float* __restrict__ h1,
                                                  const float* __restrict__ wdn,
                                                  const float* __restrict__ act,
                                                  const float* __restrict__ w2,
                                                  float* __restrict__ out) {
    const int bid = blockIdx.x;
    if (bid < NB_M1) {
        mm_body<1>(bid % (HIDDEN / 128), bid / (HIDDEN / 128),
                   h1, wdn, out, SHINTER, HIDDEN);
    } else {
        const int b = bid - NB_M1;
        mm_body<3>(b % (HIDDEN / 128), b / (HIDDEN / 128),
                   act, w2, out, INTER, HIDDEN);
    }
}

// ---------------------------------------------------------------------------
extern "C" void kernel_launch(void* const* d_in, const int* in_sizes, int n_in,
                              void* d_out, int out_size) {
    const float* x   = (const float*)d_in[0];
    const float* gw  = (const float*)d_in[1];
    const float* gb  = (const float*)d_in[2];
    const float* wup = (const float*)d_in[3];
    const float* wdn = (const float*)d_in[4];
    const float* w1  = (const float*)d_in[5];
    const float* w2  = (const float*)d_in[6];
    float* out = (float*)d_out;

    const int T = in_sizes[0] / HIDDEN;      // 1024

    float* h1 = nullptr;
    cudaGetSymbolAddress((void**)&h1, g_h1);
    float* act = nullptr;
    cudaGetSymbolAddress((void**)&act, g_act);

    cudaFuncSetAttribute(k_fuseA, cudaFuncAttributeMaxDynamicSharedMemorySize, SMEM_BYTES);
    cudaFuncSetAttribute(k_fuseB, cudaFuncAttributeMaxDynamicSharedMemorySize, SMEM_BYTES);

    k_zero<<<1, 64>>>();
    k_gate<<<T, 64>>>(x, gw, gb);
    k_scan<<<1, 32>>>();
    cudaMemsetAsync(out, 0, (size_t)out_size * sizeof(float));

    k_fuseA<<<NB_M0 + NB_M2, 256, SMEM_BYTES>>>(x, wup, h1, w1, act);
    k_fuseB<<<NB_M1 + NB_M3, 256, SMEM_BYTES>>>(h1, wdn, act, w2, out);
}